// round 8
// baseline (speedup 1.0000x reference)
#include <cuda_runtime.h>
#include <cuda_bf16.h>
#include <math.h>
#include <stdint.h>

#define D_FEAT 64
#define HID    256
#define NMAX   500000
#define EMAX   2000000
#define ECAP   64

// ---------------- scratch (static device globals) -----------------------------
__device__ int   g_flag[NMAX];
__device__ int   g_cnt[NMAX];
__device__ int   g_uniq[NMAX];
__device__ int   g_uniq_count;
__device__ int   g_es[(size_t)NMAX * ECAP];
__device__ __align__(256) float g_hneigh[(size_t)NMAX * D_FEAT];
__device__ __align__(16) __nv_bfloat16 g_w1s[2][2][D_FEAT * HID];
__device__ __align__(16) __nv_bfloat16 g_w2s[2][2][HID * D_FEAT];

// ---------------- K1: init -----------------------------------------------------
__global__ void k_init(int N) {
    int i = blockIdx.x * blockDim.x + threadIdx.x;
    if (i == 0) g_uniq_count = 0;
    if (i < N) { g_flag[i] = 0; g_cnt[i] = 0; }
}

// ---------------- K2: mark targets, assign compact uids ------------------------
__global__ void k_mark(const int* __restrict__ targets, int T) {
    int i = blockIdx.x * blockDim.x + threadIdx.x;
    if (i < T) {
        int n = targets[i];
        if (atomicCAS(&g_flag[n], 0, 1) == 0) {
            int p = atomicAdd(&g_uniq_count, 1);
            g_uniq[p] = n;
            g_flag[n] = p + 2;
        }
    }
}

// ---------------- K3: bucket flagged edges into per-uid slot arrays ------------
__global__ void k_build(const int* __restrict__ src, const int* __restrict__ dst, int E) {
    int e = blockIdx.x * blockDim.x + threadIdx.x;
    if (e < E) {
        int f = g_flag[dst[e]];
        if (f >= 2) {
            int uid  = f - 2;
            int slot = atomicAdd(&g_cnt[uid], 1);
            if (slot < ECAP) g_es[(size_t)uid * ECAP + slot] = src[e];
        }
    }
}

// ---------------- K4: warp-per-node, 8-deep batched online softmax gather ------
__global__ void k_gather(const float* __restrict__ h,
                         const float* __restrict__ attn) {
    int gw   = (blockIdx.x * blockDim.x + threadIdx.x) >> 5;
    int lane = threadIdx.x & 31;
    if (gw >= g_uniq_count) return;
    int n   = g_uniq[gw];
    int cnt = g_cnt[gw];
    if (cnt > ECAP) cnt = ECAP;

    float2 a = ((const float2*)attn)[lane];
    const int* es = g_es + (size_t)gw * ECAP;

    float m = -1e30f, s = 0.f, acc0 = 0.f, acc1 = 0.f;

    for (int base = 0; base < cnt; base += 8) {
        int take = cnt - base; if (take > 8) take = 8;
        int idx[8];
        if (take == 8) {
            int4 v0 = *(const int4*)(es + base);
            int4 v1 = *(const int4*)(es + base + 4);
            idx[0] = v0.x; idx[1] = v0.y; idx[2] = v0.z; idx[3] = v0.w;
            idx[4] = v1.x; idx[5] = v1.y; idx[6] = v1.z; idx[7] = v1.w;
        } else {
            #pragma unroll
            for (int j = 0; j < 8; ++j)
                idx[j] = (j < take) ? es[base + j] : es[base];
        }
        float2 r[8];
        #pragma unroll
        for (int j = 0; j < 8; ++j) {
            if (j < take) r[j] = ((const float2*)(h + (size_t)idx[j] * D_FEAT))[lane];
            else          r[j] = make_float2(0.f, 0.f);
        }
        float p[8];
        #pragma unroll
        for (int j = 0; j < 8; ++j) p[j] = r[j].x * a.x + r[j].y * a.y;
        #pragma unroll
        for (int off = 16; off; off >>= 1) {
            #pragma unroll
            for (int j = 0; j < 8; ++j)
                p[j] += __shfl_xor_sync(0xffffffffu, p[j], off);
        }
        #pragma unroll
        for (int j = 0; j < 8; ++j) {
            if (j < take) {
                float ev = fmaxf(p[j], 0.f);
                float mn = fmaxf(m, ev);
                float cc = __expf(m - mn);
                float w  = __expf(ev - mn);
                s    = s    * cc + w;
                acc0 = acc0 * cc + r[j].x * w;
                acc1 = acc1 * cc + r[j].y * w;
                m = mn;
            }
        }
    }

    float inv = (s > 0.f) ? (1.0f / s) : 0.f;
    ((float2*)(g_hneigh + (size_t)n * D_FEAT))[lane] = make_float2(acc0 * inv, acc1 * inv);
}

// ---------------- K5: weight split (bf16 hi/lo) --------------------------------
__global__ void k_wprep(const float* __restrict__ Ws1, const float* __restrict__ Ws2,
                        const float* __restrict__ Wn1, const float* __restrict__ Wn2) {
    int i = blockIdx.x * blockDim.x + threadIdx.x;
    if (i >= 2 * 16384) return;
    int p = i >> 14;
    int j = i & 16383;
    {
        float w = (p ? Wn1 : Ws1)[j];
        __nv_bfloat16 hb = __float2bfloat16(w);
        g_w1s[p][0][j] = hb;
        g_w1s[p][1][j] = __float2bfloat16(w - __bfloat162float(hb));
    }
    {
        float w = (p ? Wn2 : Ws2)[j];
        __nv_bfloat16 hb = __float2bfloat16(w);
        g_w2s[p][0][j] = hb;
        g_w2s[p][1][j] = __float2bfloat16(w - __bfloat162float(hb));
    }
}

// ---------------- mma.sync helpers ---------------------------------------------
__device__ __forceinline__ uint32_t smem_u32(const void* p) {
    uint32_t a;
    asm("{ .reg .u64 t; cvta.to.shared.u64 t, %1; cvt.u32.u64 %0, t; }" : "=r"(a) : "l"(p));
    return a;
}
__device__ __forceinline__ void ldm4t(uint32_t addr, uint32_t& r0, uint32_t& r1,
                                      uint32_t& r2, uint32_t& r3) {
    asm volatile("ldmatrix.sync.aligned.m8n8.x4.trans.shared.b16 {%0,%1,%2,%3}, [%4];"
                 : "=r"(r0), "=r"(r1), "=r"(r2), "=r"(r3) : "r"(addr));
}
__device__ __forceinline__ void mma16816(float c[4],
                                         uint32_t a0, uint32_t a1, uint32_t a2, uint32_t a3,
                                         uint32_t b0, uint32_t b1) {
    asm volatile(
        "mma.sync.aligned.m16n8k16.row.col.f32.bf16.bf16.f32 "
        "{%0,%1,%2,%3}, {%4,%5,%6,%7}, {%8,%9}, {%0,%1,%2,%3};"
        : "+f"(c[0]), "+f"(c[1]), "+f"(c[2]), "+f"(c[3])
        : "r"(a0), "r"(a1), "r"(a2), "r"(a3), "r"(b0), "r"(b1));
}

// ---------------- K6: persistent dual-MLP, M=32/warp, 256 rows/tile -------------
#define XS    72
#define W1S   264
#define W2S   72
#define OFF_XH   0
#define OFF_XL   36864
#define OFF_W1H  73728
#define OFF_W1L  107520
#define OFF_W2H  141312
#define OFF_W2L  178176
#define OFF_B1   215040
#define OFF_B2   216064
#define SMEM_TOTAL 216320

__global__ void __launch_bounds__(256, 1)
k_mlp_mma(const float* __restrict__ cell,
          const float* __restrict__ bn1, const float* __restrict__ bn2,
          const float* __restrict__ bs1, const float* __restrict__ bs2,
          const int*   __restrict__ targets,
          float* __restrict__ out, int T, int ntiles) {
    extern __shared__ char smem[];
    const uint32_t sb = smem_u32(smem);

    const int tid  = threadIdx.x;
    const int lane = tid & 31;
    const int warp = tid >> 5;
    const int g = lane >> 2;
    const int t = lane & 3;
    const int R0 = warp * 32;

    const int lr = (lane & 7) + ((lane >> 3) & 1) * 8;
    const int lc = (lane >> 4) * 8;

    if (tid < 64) ((float*)(smem + OFF_B2))[tid] = bs2[tid] + bn2[tid];

    #pragma unroll 1
    for (int p = 0; p < 2; ++p) {
        __syncthreads();
        // ---- stage this path's W1/W2 (hi/lo) + b1, once per path ----
        {
            const uint4* s1h = (const uint4*)&g_w1s[p][0][0];
            const uint4* s1l = (const uint4*)&g_w1s[p][1][0];
            #pragma unroll
            for (int i = 0; i < 8; ++i) {
                int u = tid + 256 * i;
                int j = u * 8;
                int k = j >> 8, n = j & 255;
                uint32_t off = (k * W1S + n) * 2;
                *(uint4*)(smem + OFF_W1H + off) = s1h[u];
                *(uint4*)(smem + OFF_W1L + off) = s1l[u];
            }
            const uint4* s2h = (const uint4*)&g_w2s[p][0][0];
            const uint4* s2l = (const uint4*)&g_w2s[p][1][0];
            #pragma unroll
            for (int i = 0; i < 8; ++i) {
                int u = tid + 256 * i;
                int j = u * 8;
                int k = j >> 6, n = j & 63;
                uint32_t off = (k * W2S + n) * 2;
                *(uint4*)(smem + OFF_W2H + off) = s2h[u];
                *(uint4*)(smem + OFF_W2L + off) = s2l[u];
            }
            const float* b1p = p ? bn1 : bs1;
            ((float*)(smem + OFF_B1))[tid] = b1p[tid];
        }
        __syncthreads();

        const float* b1s = (const float*)(smem + OFF_B1);
        const uint32_t w1h = sb + OFF_W1H, w1l = sb + OFF_W1L;
        const uint32_t w2h = sb + OFF_W2H, w2l = sb + OFF_W2L;

        // ---- persistent tile loop ----
        #pragma unroll 1
        for (int tile = blockIdx.x; tile < ntiles; tile += gridDim.x) {
            // ---- stage X (hi/lo bf16), one thread per row ----
            {
                size_t tgt = (size_t)tile * 256 + tid;
                if (tgt >= (size_t)T) tgt = (size_t)T - 1;
                const int node = targets[tgt];
                const float4* xv = (const float4*)(p ? (g_hneigh + (size_t)node * 64)
                                                     : (cell     + (size_t)node * 64));
                uint32_t base = (uint32_t)tid * XS;
                #pragma unroll
                for (int q = 0; q < 16; ++q) {
                    float4 v = xv[q];
                    __nv_bfloat16 h0 = __float2bfloat16(v.x), h1 = __float2bfloat16(v.y);
                    __nv_bfloat16 h2 = __float2bfloat16(v.z), h3 = __float2bfloat16(v.w);
                    float l0 = v.x - __bfloat162float(h0), l1 = v.y - __bfloat162float(h1);
                    float l2 = v.z - __bfloat162float(h2), l3 = v.w - __bfloat162float(h3);
                    __nv_bfloat162 hv0 = __halves2bfloat162(h0, h1);
                    __nv_bfloat162 hv1 = __halves2bfloat162(h2, h3);
                    __nv_bfloat162 lv0 = __halves2bfloat162(__float2bfloat16(l0), __float2bfloat16(l1));
                    __nv_bfloat162 lv1 = __halves2bfloat162(__float2bfloat16(l2), __float2bfloat16(l3));
                    uint32_t off = (base + 4 * q) * 2;
                    *(uint32_t*)(smem + OFF_XH + off)     = *(uint32_t*)&hv0;
                    *(uint32_t*)(smem + OFF_XH + off + 4) = *(uint32_t*)&hv1;
                    *(uint32_t*)(smem + OFF_XL + off)     = *(uint32_t*)&lv0;
                    *(uint32_t*)(smem + OFF_XL + off + 4) = *(uint32_t*)&lv1;
                }
            }
            __syncthreads();

            // ---- A1 fragments ----
            uint32_t a1h[2][4][4], a1l[2][4][4];
            #pragma unroll
            for (int tau = 0; tau < 2; ++tau)
                #pragma unroll
                for (int kk = 0; kk < 4; ++kk) {
                    uint32_t c0 = ((R0 + 16 * tau + g) * XS + kk * 16 + 2 * t) * 2;
                    uint32_t c1 = c0 + 8 * XS * 2;
                    a1h[tau][kk][0] = *(uint32_t*)(smem + OFF_XH + c0);
                    a1h[tau][kk][1] = *(uint32_t*)(smem + OFF_XH + c1);
                    a1h[tau][kk][2] = *(uint32_t*)(smem + OFF_XH + c0 + 16);
                    a1h[tau][kk][3] = *(uint32_t*)(smem + OFF_XH + c1 + 16);
                    a1l[tau][kk][0] = *(uint32_t*)(smem + OFF_XL + c0);
                    a1l[tau][kk][1] = *(uint32_t*)(smem + OFF_XL + c1);
                    a1l[tau][kk][2] = *(uint32_t*)(smem + OFF_XL + c0 + 16);
                    a1l[tau][kk][3] = *(uint32_t*)(smem + OFF_XL + c1 + 16);
                }

            float o[2][8][4];
            #pragma unroll
            for (int tau = 0; tau < 2; ++tau)
                #pragma unroll
                for (int j = 0; j < 8; ++j)
                    #pragma unroll
                    for (int q = 0; q < 4; ++q) o[tau][j][q] = 0.f;

            #pragma unroll 1
            for (int n16 = 0; n16 < 16; ++n16) {
                float c[2][2][4];
                #pragma unroll
                for (int tau = 0; tau < 2; ++tau)
                    #pragma unroll
                    for (int hh = 0; hh < 2; ++hh)
                        #pragma unroll
                        for (int q = 0; q < 4; ++q) c[tau][hh][q] = 0.f;

                #pragma unroll
                for (int kk = 0; kk < 4; ++kk) {
                    uint32_t lm = ((kk * 16 + lr) * W1S + n16 * 16 + lc) * 2;
                    uint32_t bh0, bh1, bh2, bh3, bl0, bl1, bl2, bl3;
                    ldm4t(w1h + lm, bh0, bh1, bh2, bh3);
                    ldm4t(w1l + lm, bl0, bl1, bl2, bl3);
                    #pragma unroll
                    for (int tau = 0; tau < 2; ++tau) {
                        mma16816(c[tau][0], a1h[tau][kk][0], a1h[tau][kk][1], a1h[tau][kk][2], a1h[tau][kk][3], bh0, bh1);
                        mma16816(c[tau][1], a1h[tau][kk][0], a1h[tau][kk][1], a1h[tau][kk][2], a1h[tau][kk][3], bh2, bh3);
                        mma16816(c[tau][0], a1h[tau][kk][0], a1h[tau][kk][1], a1h[tau][kk][2], a1h[tau][kk][3], bl0, bl1);
                        mma16816(c[tau][1], a1h[tau][kk][0], a1h[tau][kk][1], a1h[tau][kk][2], a1h[tau][kk][3], bl2, bl3);
                        mma16816(c[tau][0], a1l[tau][kk][0], a1l[tau][kk][1], a1l[tau][kk][2], a1l[tau][kk][3], bh0, bh1);
                        mma16816(c[tau][1], a1l[tau][kk][0], a1l[tau][kk][1], a1l[tau][kk][2], a1l[tau][kk][3], bh2, bh3);
                    }
                }

                uint32_t a2h[2][4], a2l[2][4];
                {
                    float vb0 = b1s[n16 * 16 + 2 * t];
                    float vb1 = b1s[n16 * 16 + 2 * t + 1];
                    float vb2 = b1s[n16 * 16 + 8 + 2 * t];
                    float vb3 = b1s[n16 * 16 + 8 + 2 * t + 1];
                    #pragma unroll
                    for (int tau = 0; tau < 2; ++tau) {
                        float v[8];
                        v[0] = fmaxf(c[tau][0][0] + vb0, 0.f); v[1] = fmaxf(c[tau][0][1] + vb1, 0.f);
                        v[2] = fmaxf(c[tau][0][2] + vb0, 0.f); v[3] = fmaxf(c[tau][0][3] + vb1, 0.f);
                        v[4] = fmaxf(c[tau][1][0] + vb2, 0.f); v[5] = fmaxf(c[tau][1][1] + vb3, 0.f);
                        v[6] = fmaxf(c[tau][1][2] + vb2, 0.f); v[7] = fmaxf(c[tau][1][3] + vb3, 0.f);
                        #pragma unroll
                        for (int q = 0; q < 4; ++q) {
                            float v0 = v[2 * q], v1 = v[2 * q + 1];
                            __nv_bfloat16 h0 = __float2bfloat16(v0), h1 = __float2bfloat16(v1);
                            float l0 = v0 - __bfloat162float(h0);
                            float l1 = v1 - __bfloat162float(h1);
                            __nv_bfloat162 hv = __halves2bfloat162(h0, h1);
                            __nv_bfloat162 lv = __halves2bfloat162(__float2bfloat16(l0), __float2bfloat16(l1));
                            a2h[tau][q] = *(uint32_t*)&hv;
                            a2l[tau][q] = *(uint32_t*)&lv;
                        }
                    }
                }

                #pragma unroll
                for (int m = 0; m < 4; ++m) {
                    uint32_t lm = ((n16 * 16 + lr) * W2S + m * 16 + lc) * 2;
                    uint32_t bh0, bh1, bh2, bh3, bl0, bl1, bl2, bl3;
                    ldm4t(w2h + lm, bh0, bh1, bh2, bh3);
                    ldm4t(w2l + lm, bl0, bl1, bl2, bl3);
                    #pragma unroll
                    for (int tau = 0; tau < 2; ++tau) {
                        mma16816(o[tau][2 * m],     a2h[tau][0], a2h[tau][1], a2h[tau][2], a2h[tau][3], bh0, bh1);
                        mma16816(o[tau][2 * m + 1], a2h[tau][0], a2h[tau][1], a2h[tau][2], a2h[tau][3], bh2, bh3);
                        mma16816(o[tau][2 * m],     a2h[tau][0], a2h[tau][1], a2h[tau][2], a2h[tau][3], bl0, bl1);
                        mma16816(o[tau][2 * m + 1], a2h[tau][0], a2h[tau][1], a2h[tau][2], a2h[tau][3], bl2, bl3);
                        mma16816(o[tau][2 * m],     a2l[tau][0], a2l[tau][1], a2l[tau][2], a2l[tau][3], bh0, bh1);
                        mma16816(o[tau][2 * m + 1], a2l[tau][0], a2l[tau][1], a2l[tau][2], a2l[tau][3], bh2, bh3);
                    }
                }
            }

            // ---- epilogue: p=0 store partial; p=1 add partial + b2, relu ----
            const float* b2c = (const float*)(smem + OFF_B2);
            #pragma unroll
            for (int tau = 0; tau < 2; ++tau) {
                size_t r0 = (size_t)tile * 256 + R0 + 16 * tau + g;
                size_t r1 = r0 + 8;
                #pragma unroll
                for (int j = 0; j < 8; ++j) {
                    int col = 8 * j + 2 * t;
                    if (p == 0) {
                        if (r0 < (size_t)T)
                            *(float2*)(out + r0 * 64 + col) = make_float2(o[tau][j][0], o[tau][j][1]);
                        if (r1 < (size_t)T)
                            *(float2*)(out + r1 * 64 + col) = make_float2(o[tau][j][2], o[tau][j][3]);
                    } else {
                        float bb0 = b2c[col], bb1 = b2c[col + 1];
                        if (r0 < (size_t)T) {
                            float2 s = *(float2*)(out + r0 * 64 + col);
                            *(float2*)(out + r0 * 64 + col) =
                                make_float2(fmaxf(s.x + o[tau][j][0] + bb0, 0.f),
                                            fmaxf(s.y + o[tau][j][1] + bb1, 0.f));
                        }
                        if (r1 < (size_t)T) {
                            float2 s = *(float2*)(out + r1 * 64 + col);
                            *(float2*)(out + r1 * 64 + col) =
                                make_float2(fmaxf(s.x + o[tau][j][2] + bb0, 0.f),
                                            fmaxf(s.y + o[tau][j][3] + bb1, 0.f));
                        }
                    }
                }
            }
            __syncthreads();   // X buffer reuse safe
        }
    }
}

// ---------------- launch --------------------------------------------------------
extern "C" void kernel_launch(void* const* d_in, const int* in_sizes, int n_in,
                              void* d_out, int out_size) {
    const float* h    = (const float*)d_in[0];
    const float* cell = (const float*)d_in[1];
    const float* attn = (const float*)d_in[2];
    const float* Wn1  = (const float*)d_in[3];
    const float* bn1  = (const float*)d_in[4];
    const float* Wn2  = (const float*)d_in[5];
    const float* bn2  = (const float*)d_in[6];
    const float* Ws1  = (const float*)d_in[7];
    const float* bs1  = (const float*)d_in[8];
    const float* Ws2  = (const float*)d_in[9];
    const float* bs2  = (const float*)d_in[10];
    const int* src     = (const int*)d_in[11];
    const int* dst     = (const int*)d_in[12];
    const int* targets = (const int*)d_in[13];

    int N = in_sizes[0] / D_FEAT;
    int E = in_sizes[11];
    int T = in_sizes[13];
    float* out = (float*)d_out;

    k_init <<<(N + 255) / 256, 256>>>(N);
    k_mark <<<(T + 255) / 256, 256>>>(targets, T);
    k_build<<<(E + 255) / 256, 256>>>(src, dst, E);

    int gwarps = (T < N) ? T : N;
    k_gather<<<(gwarps + 7) / 8, 256>>>(h, attn);

    k_wprep<<<(2 * 16384 + 255) / 256, 256>>>(Ws1, Ws2, Wn1, Wn2);

    int ntiles = (T + 255) / 256;
    int grid = ntiles < 148 ? ntiles : 148;
    cudaFuncSetAttribute(k_mlp_mma, cudaFuncAttributeMaxDynamicSharedMemorySize, SMEM_TOTAL);
    k_mlp_mma<<<grid, 256, SMEM_TOTAL>>>(cell, bn1, bn2, bs1, bs2,
                                         targets, out, T, ntiles);
}

// round 12
// speedup vs baseline: 1.2328x; 1.2328x over previous
#include <cuda_runtime.h>
#include <cuda_fp16.h>
#include <math.h>
#include <stdint.h>

#define D_FEAT 64
#define HID    256
#define NMAX   500000
#define EMAX   2000000
#define ECAP   64

// ---------------- scratch (static device globals) -----------------------------
__device__ int   g_flag[NMAX];
__device__ int   g_cnt[NMAX];
__device__ int   g_uniq[NMAX];
__device__ int   g_uniq_count;
__device__ int   g_es[(size_t)NMAX * ECAP];
__device__ __align__(256) float g_hneigh[(size_t)NMAX * D_FEAT];

// ---------------- K1: init -----------------------------------------------------
__global__ void k_init(int N) {
    int i = blockIdx.x * blockDim.x + threadIdx.x;
    if (i == 0) g_uniq_count = 0;
    if (i < N) { g_flag[i] = 0; g_cnt[i] = 0; }
}

// ---------------- K2: mark targets, assign compact uids ------------------------
__global__ void k_mark(const int* __restrict__ targets, int T) {
    int i = blockIdx.x * blockDim.x + threadIdx.x;
    if (i < T) {
        int n = targets[i];
        if (atomicCAS(&g_flag[n], 0, 1) == 0) {
            int p = atomicAdd(&g_uniq_count, 1);
            g_uniq[p] = n;
            g_flag[n] = p + 2;
        }
    }
}

// ---------------- K3: bucket flagged edges into per-uid slot arrays ------------
__global__ void k_build(const int* __restrict__ src, const int* __restrict__ dst, int E) {
    int e = blockIdx.x * blockDim.x + threadIdx.x;
    if (e < E) {
        int f = g_flag[dst[e]];
        if (f >= 2) {
            int uid  = f - 2;
            int slot = atomicAdd(&g_cnt[uid], 1);
            if (slot < ECAP) g_es[(size_t)uid * ECAP + slot] = src[e];
        }
    }
}

// ---------------- K4: warp-per-node, degree-adaptive chunked gather ------------
template<int CH>
__device__ __forceinline__ void gather_chunk(const float* __restrict__ h,
                                             const int* __restrict__ es, int base,
                                             float2 a, int lane,
                                             float& m, float& s, float& acc0, float& acc1) {
    int idx[CH];
    #pragma unroll
    for (int j = 0; j < CH; ++j) idx[j] = es[base + j];
    float2 r[CH];
    #pragma unroll
    for (int j = 0; j < CH; ++j)
        r[j] = ((const float2*)(h + (size_t)idx[j] * D_FEAT))[lane];
    float p[CH];
    #pragma unroll
    for (int j = 0; j < CH; ++j) p[j] = r[j].x * a.x + r[j].y * a.y;
    #pragma unroll
    for (int off = 16; off; off >>= 1) {
        #pragma unroll
        for (int j = 0; j < CH; ++j)
            p[j] += __shfl_xor_sync(0xffffffffu, p[j], off);
    }
    #pragma unroll
    for (int j = 0; j < CH; ++j) {
        float ev = fmaxf(p[j], 0.f);
        float mn = fmaxf(m, ev);
        float cc = __expf(m - mn);
        float w  = __expf(ev - mn);
        s    = s    * cc + w;
        acc0 = acc0 * cc + r[j].x * w;
        acc1 = acc1 * cc + r[j].y * w;
        m = mn;
    }
}

__global__ void k_gather(const float* __restrict__ h,
                         const float* __restrict__ attn) {
    int gw   = (blockIdx.x * blockDim.x + threadIdx.x) >> 5;
    int lane = threadIdx.x & 31;
    if (gw >= g_uniq_count) return;
    int n   = g_uniq[gw];
    int cnt = g_cnt[gw];
    if (cnt > ECAP) cnt = ECAP;

    float2 a = ((const float2*)attn)[lane];
    const int* es = g_es + (size_t)gw * ECAP;

    float m = -1e30f, s = 0.f, acc0 = 0.f, acc1 = 0.f;
    int base = 0, rem = cnt;
    while (rem >= 8) { gather_chunk<8>(h, es, base, a, lane, m, s, acc0, acc1); base += 8; rem -= 8; }
    if (rem >= 4)    { gather_chunk<4>(h, es, base, a, lane, m, s, acc0, acc1); base += 4; rem -= 4; }
    if (rem >= 2)    { gather_chunk<2>(h, es, base, a, lane, m, s, acc0, acc1); base += 2; rem -= 2; }
    if (rem)         { gather_chunk<1>(h, es, base, a, lane, m, s, acc0, acc1); }

    float inv = (s > 0.f) ? (1.0f / s) : 0.f;
    ((float2*)(g_hneigh + (size_t)n * D_FEAT))[lane] = make_float2(acc0 * inv, acc1 * inv);
}

// ---------------- mma.sync helpers ---------------------------------------------
__device__ __forceinline__ uint32_t smem_u32(const void* p) {
    uint32_t a;
    asm("{ .reg .u64 t; cvta.to.shared.u64 t, %1; cvt.u32.u64 %0, t; }" : "=r"(a) : "l"(p));
    return a;
}
__device__ __forceinline__ void ldm4t(uint32_t addr, uint32_t& r0, uint32_t& r1,
                                      uint32_t& r2, uint32_t& r3) {
    asm volatile("ldmatrix.sync.aligned.m8n8.x4.trans.shared.b16 {%0,%1,%2,%3}, [%4];"
                 : "=r"(r0), "=r"(r1), "=r"(r2), "=r"(r3) : "r"(addr));
}
__device__ __forceinline__ void mma16816h(float c[4],
                                          uint32_t a0, uint32_t a1, uint32_t a2, uint32_t a3,
                                          uint32_t b0, uint32_t b1) {
    asm volatile(
        "mma.sync.aligned.m16n8k16.row.col.f32.f16.f16.f32 "
        "{%0,%1,%2,%3}, {%4,%5,%6,%7}, {%8,%9}, {%0,%1,%2,%3};"
        : "+f"(c[0]), "+f"(c[1]), "+f"(c[2]), "+f"(c[3])
        : "r"(a0), "r"(a1), "r"(a2), "r"(a3), "r"(b0), "r"(b1));
}
__device__ __forceinline__ uint32_t packh2(__half a, __half b) {
    __half2 h = __halves2half2(a, b);
    return *(uint32_t*)&h;
}

// ---------------- K5/K6: single-path MLP (fp16 A-split 2-term) ------------------
// FINAL=0: path S (cell), store raw partial to out
// FINAL=1: path N (g_hneigh), out = relu(partial + o + bs2+bn2)
#define XS    72
#define W1S   264
#define W2S   72
#define OFF_XH   0
#define OFF_XL   36864
#define OFF_W1   73728
#define OFF_W2   107520
#define OFF_B1   144384
#define OFF_B2   145408
#define SMEM_TOTAL 145664

template<int FINAL>
__global__ void __launch_bounds__(256, 1)
k_mlp_half(const float* __restrict__ x_src,
           const float* __restrict__ W1, const float* __restrict__ b1g,
           const float* __restrict__ W2,
           const float* __restrict__ bs2, const float* __restrict__ bn2,
           const int*   __restrict__ targets,
           float* __restrict__ out, int T) {
    extern __shared__ char smem[];
    const uint32_t sb = smem_u32(smem);

    const int tid  = threadIdx.x;
    const int lane = tid & 31;
    const int warp = tid >> 5;
    const int g = lane >> 2;
    const int t = lane & 3;
    const int R0 = warp * 32;

    const int lr = (lane & 7) + ((lane >> 3) & 1) * 8;
    const int lc = (lane >> 4) * 8;

    if (FINAL && tid < 64) ((float*)(smem + OFF_B2))[tid] = bs2[tid] + bn2[tid];

    // ---- stage X (fp16 hi/lo), one thread per row ----
    {
        size_t tgt = (size_t)blockIdx.x * 256 + tid;
        if (tgt >= (size_t)T) tgt = (size_t)T - 1;
        const int node = targets[tgt];
        const float* xr = FINAL ? (g_hneigh + (size_t)node * 64)
                                : (x_src    + (size_t)node * 64);
        const float4* xv = (const float4*)xr;
        uint32_t base = (uint32_t)tid * XS;
        #pragma unroll
        for (int q = 0; q < 16; ++q) {
            float4 v = xv[q];
            __half h0 = __float2half(v.x), h1 = __float2half(v.y);
            __half h2 = __float2half(v.z), h3 = __float2half(v.w);
            float l0 = v.x - __half2float(h0), l1 = v.y - __half2float(h1);
            float l2 = v.z - __half2float(h2), l3 = v.w - __half2float(h3);
            uint32_t off = (base + 4 * q) * 2;
            *(uint32_t*)(smem + OFF_XH + off)     = packh2(h0, h1);
            *(uint32_t*)(smem + OFF_XH + off + 4) = packh2(h2, h3);
            *(uint32_t*)(smem + OFF_XL + off)     = packh2(__float2half(l0), __float2half(l1));
            *(uint32_t*)(smem + OFF_XL + off + 4) = packh2(__float2half(l2), __float2half(l3));
        }
    }
    // ---- stage W1/W2 (fp32 -> fp16 on the fly) + b1 ----
    {
        const float4* w1v = (const float4*)W1;   // [k*256+n], 4096 float4
        #pragma unroll
        for (int i = 0; i < 16; ++i) {
            int u = tid + 256 * i;
            int j = u * 4;
            int k = j >> 8, n = j & 255;
            float4 v = w1v[u];
            uint32_t off = (k * W1S + n) * 2;
            *(uint32_t*)(smem + OFF_W1 + off)     = packh2(__float2half(v.x), __float2half(v.y));
            *(uint32_t*)(smem + OFF_W1 + off + 4) = packh2(__float2half(v.z), __float2half(v.w));
        }
        const float4* w2v = (const float4*)W2;   // [k*64+n], 4096 float4
        #pragma unroll
        for (int i = 0; i < 16; ++i) {
            int u = tid + 256 * i;
            int j = u * 4;
            int k = j >> 6, n = j & 63;
            float4 v = w2v[u];
            uint32_t off = (k * W2S + n) * 2;
            *(uint32_t*)(smem + OFF_W2 + off)     = packh2(__float2half(v.x), __float2half(v.y));
            *(uint32_t*)(smem + OFF_W2 + off + 4) = packh2(__float2half(v.z), __float2half(v.w));
        }
        ((float*)(smem + OFF_B1))[tid] = b1g[tid];
    }
    __syncthreads();

    // ---- A1 fragments: 2 row-tiles x K=64, hi & lo ----
    uint32_t a1h[2][4][4], a1l[2][4][4];
    #pragma unroll
    for (int tau = 0; tau < 2; ++tau)
        #pragma unroll
        for (int kk = 0; kk < 4; ++kk) {
            uint32_t c0 = ((R0 + 16 * tau + g) * XS + kk * 16 + 2 * t) * 2;
            uint32_t c1 = c0 + 8 * XS * 2;
            a1h[tau][kk][0] = *(uint32_t*)(smem + OFF_XH + c0);
            a1h[tau][kk][1] = *(uint32_t*)(smem + OFF_XH + c1);
            a1h[tau][kk][2] = *(uint32_t*)(smem + OFF_XH + c0 + 16);
            a1h[tau][kk][3] = *(uint32_t*)(smem + OFF_XH + c1 + 16);
            a1l[tau][kk][0] = *(uint32_t*)(smem + OFF_XL + c0);
            a1l[tau][kk][1] = *(uint32_t*)(smem + OFF_XL + c1);
            a1l[tau][kk][2] = *(uint32_t*)(smem + OFF_XL + c0 + 16);
            a1l[tau][kk][3] = *(uint32_t*)(smem + OFF_XL + c1 + 16);
        }

    float o[2][8][4];
    #pragma unroll
    for (int tau = 0; tau < 2; ++tau)
        #pragma unroll
        for (int j = 0; j < 8; ++j)
            #pragma unroll
            for (int q = 0; q < 4; ++q) o[tau][j][q] = 0.f;

    const float* b1s = (const float*)(smem + OFF_B1);
    const uint32_t w1a = sb + OFF_W1, w2a = sb + OFF_W2;

    #pragma unroll 1
    for (int n16 = 0; n16 < 16; ++n16) {
        float c[2][2][4];
        #pragma unroll
        for (int tau = 0; tau < 2; ++tau)
            #pragma unroll
            for (int hh = 0; hh < 2; ++hh)
                #pragma unroll
                for (int q = 0; q < 4; ++q) c[tau][hh][q] = 0.f;

        // ---- layer 1 (2 terms: Ah*B + Al*B) ----
        #pragma unroll
        for (int kk = 0; kk < 4; ++kk) {
            uint32_t lm = ((kk * 16 + lr) * W1S + n16 * 16 + lc) * 2;
            uint32_t b0, b1, b2, b3;
            ldm4t(w1a + lm, b0, b1, b2, b3);
            #pragma unroll
            for (int tau = 0; tau < 2; ++tau) {
                mma16816h(c[tau][0], a1h[tau][kk][0], a1h[tau][kk][1], a1h[tau][kk][2], a1h[tau][kk][3], b0, b1);
                mma16816h(c[tau][1], a1h[tau][kk][0], a1h[tau][kk][1], a1h[tau][kk][2], a1h[tau][kk][3], b2, b3);
                mma16816h(c[tau][0], a1l[tau][kk][0], a1l[tau][kk][1], a1l[tau][kk][2], a1l[tau][kk][3], b0, b1);
                mma16816h(c[tau][1], a1l[tau][kk][0], a1l[tau][kk][1], a1l[tau][kk][2], a1l[tau][kk][3], b2, b3);
            }
        }

        // ---- epilogue: +b1, relu, fp16 hi/lo split -> A2 frags ----
        uint32_t a2h[2][4], a2l[2][4];
        {
            float vb0 = b1s[n16 * 16 + 2 * t];
            float vb1 = b1s[n16 * 16 + 2 * t + 1];
            float vb2 = b1s[n16 * 16 + 8 + 2 * t];
            float vb3 = b1s[n16 * 16 + 8 + 2 * t + 1];
            #pragma unroll
            for (int tau = 0; tau < 2; ++tau) {
                float v[8];
                v[0] = fmaxf(c[tau][0][0] + vb0, 0.f); v[1] = fmaxf(c[tau][0][1] + vb1, 0.f);
                v[2] = fmaxf(c[tau][0][2] + vb0, 0.f); v[3] = fmaxf(c[tau][0][3] + vb1, 0.f);
                v[4] = fmaxf(c[tau][1][0] + vb2, 0.f); v[5] = fmaxf(c[tau][1][1] + vb3, 0.f);
                v[6] = fmaxf(c[tau][1][2] + vb2, 0.f); v[7] = fmaxf(c[tau][1][3] + vb3, 0.f);
                #pragma unroll
                for (int q = 0; q < 4; ++q) {
                    float v0 = v[2 * q], v1 = v[2 * q + 1];
                    __half h0 = __float2half(v0), h1 = __float2half(v1);
                    float l0 = v0 - __half2float(h0);
                    float l1 = v1 - __half2float(h1);
                    a2h[tau][q] = packh2(h0, h1);
                    a2l[tau][q] = packh2(__float2half(l0), __float2half(l1));
                }
            }
        }

        // ---- layer 2 (2 terms) ----
        #pragma unroll
        for (int m = 0; m < 4; ++m) {
            uint32_t lm = ((n16 * 16 + lr) * W2S + m * 16 + lc) * 2;
            uint32_t b0, b1, b2, b3;
            ldm4t(w2a + lm, b0, b1, b2, b3);
            #pragma unroll
            for (int tau = 0; tau < 2; ++tau) {
                mma16816h(o[tau][2 * m],     a2h[tau][0], a2h[tau][1], a2h[tau][2], a2h[tau][3], b0, b1);
                mma16816h(o[tau][2 * m + 1], a2h[tau][0], a2h[tau][1], a2h[tau][2], a2h[tau][3], b2, b3);
                mma16816h(o[tau][2 * m],     a2l[tau][0], a2l[tau][1], a2l[tau][2], a2l[tau][3], b0, b1);
                mma16816h(o[tau][2 * m + 1], a2l[tau][0], a2l[tau][1], a2l[tau][2], a2l[tau][3], b2, b3);
            }
        }
    }

    // ---- store: partial (S) or final add+bias+relu (N) ----
    #pragma unroll
    for (int tau = 0; tau < 2; ++tau) {
        size_t r0 = (size_t)blockIdx.x * 256 + R0 + 16 * tau + g;
        size_t r1 = r0 + 8;
        #pragma unroll
        for (int j = 0; j < 8; ++j) {
            int col = 8 * j + 2 * t;
            if (!FINAL) {
                if (r0 < (size_t)T)
                    *(float2*)(out + r0 * 64 + col) = make_float2(o[tau][j][0], o[tau][j][1]);
                if (r1 < (size_t)T)
                    *(float2*)(out + r1 * 64 + col) = make_float2(o[tau][j][2], o[tau][j][3]);
            } else {
                const float* b2c = (const float*)(smem + OFF_B2);
                float bb0 = b2c[col], bb1 = b2c[col + 1];
                if (r0 < (size_t)T) {
                    float2 s = *(float2*)(out + r0 * 64 + col);
                    *(float2*)(out + r0 * 64 + col) =
                        make_float2(fmaxf(s.x + o[tau][j][0] + bb0, 0.f),
                                    fmaxf(s.y + o[tau][j][1] + bb1, 0.f));
                }
                if (r1 < (size_t)T) {
                    float2 s = *(float2*)(out + r1 * 64 + col);
                    *(float2*)(out + r1 * 64 + col) =
                        make_float2(fmaxf(s.x + o[tau][j][2] + bb0, 0.f),
                                    fmaxf(s.y + o[tau][j][3] + bb1, 0.f));
                }
            }
        }
    }
}

// ---------------- launch --------------------------------------------------------
extern "C" void kernel_launch(void* const* d_in, const int* in_sizes, int n_in,
                              void* d_out, int out_size) {
    const float* h    = (const float*)d_in[0];
    const float* cell = (const float*)d_in[1];
    const float* attn = (const float*)d_in[2];
    const float* Wn1  = (const float*)d_in[3];
    const float* bn1  = (const float*)d_in[4];
    const float* Wn2  = (const float*)d_in[5];
    const float* bn2  = (const float*)d_in[6];
    const float* Ws1  = (const float*)d_in[7];
    const float* bs1  = (const float*)d_in[8];
    const float* Ws2  = (const float*)d_in[9];
    const float* bs2  = (const float*)d_in[10];
    const int* src     = (const int*)d_in[11];
    const int* dst     = (const int*)d_in[12];
    const int* targets = (const int*)d_in[13];

    int N = in_sizes[0] / D_FEAT;
    int E = in_sizes[11];
    int T = in_sizes[13];
    float* out = (float*)d_out;

    k_init <<<(N + 255) / 256, 256>>>(N);
    k_mark <<<(T + 255) / 256, 256>>>(targets, T);
    k_build<<<(E + 255) / 256, 256>>>(src, dst, E);

    int mgrid = (T + 255) / 256;
    cudaFuncSetAttribute(k_mlp_half<0>, cudaFuncAttributeMaxDynamicSharedMemorySize, SMEM_TOTAL);
    cudaFuncSetAttribute(k_mlp_half<1>, cudaFuncAttributeMaxDynamicSharedMemorySize, SMEM_TOTAL);

    // path S (independent of gather) — 4th launch, gets profiled
    k_mlp_half<0><<<mgrid, 256, SMEM_TOTAL>>>(cell, Ws1, bs1, Ws2, bs2, bn2,
                                              targets, out, T);

    int gwarps = (T < N) ? T : N;
    k_gather<<<(gwarps + 7) / 8, 256>>>(h, attn);

    // path N: add partial, bias, relu
    k_mlp_half<1><<<mgrid, 256, SMEM_TOTAL>>>(nullptr, Wn1, bn1, Wn2, bs2, bn2,
                                              targets, out, T);
}

// round 13
// speedup vs baseline: 1.2755x; 1.0346x over previous
#include <cuda_runtime.h>
#include <cuda_fp16.h>
#include <math.h>
#include <stdint.h>

#define D_FEAT 64
#define HID    256
#define NMAX   500000
#define EMAX   2000000
#define ECAP   64

// ---------------- scratch (static device globals) -----------------------------
__device__ int   g_flag[NMAX];
__device__ int   g_cnt[NMAX];
__device__ int   g_uniq[NMAX];
__device__ int   g_uniq_count;
__device__ int   g_es[(size_t)NMAX * ECAP];
__device__ __align__(256) float g_hneigh[(size_t)NMAX * D_FEAT];

// ---------------- K1: init -----------------------------------------------------
__global__ void k_init(int N) {
    int i = blockIdx.x * blockDim.x + threadIdx.x;
    if (i == 0) g_uniq_count = 0;
    if (i < N) { g_flag[i] = 0; g_cnt[i] = 0; }
}

// ---------------- K2: mark targets, assign compact uids ------------------------
__global__ void k_mark(const int* __restrict__ targets, int T) {
    int i = blockIdx.x * blockDim.x + threadIdx.x;
    if (i < T) {
        int n = targets[i];
        if (atomicCAS(&g_flag[n], 0, 1) == 0) {
            int p = atomicAdd(&g_uniq_count, 1);
            g_uniq[p] = n;
            g_flag[n] = p + 2;
        }
    }
}

// ---------------- K3: bucket flagged edges into per-uid slot arrays ------------
__global__ void k_build(const int* __restrict__ src, const int* __restrict__ dst, int E) {
    int e = blockIdx.x * blockDim.x + threadIdx.x;
    if (e < E) {
        int f = g_flag[dst[e]];
        if (f >= 2) {
            int uid  = f - 2;
            int slot = atomicAdd(&g_cnt[uid], 1);
            if (slot < ECAP) g_es[(size_t)uid * ECAP + slot] = src[e];
        }
    }
}

// ---------------- K4: warp-per-node, degree-adaptive chunked gather ------------
template<int CH>
__device__ __forceinline__ void gather_chunk(const float* __restrict__ h,
                                             const int* __restrict__ es, int base,
                                             float2 a, int lane,
                                             float& m, float& s, float& acc0, float& acc1) {
    int idx[CH];
    #pragma unroll
    for (int j = 0; j < CH; ++j) idx[j] = es[base + j];
    float2 r[CH];
    #pragma unroll
    for (int j = 0; j < CH; ++j)
        r[j] = ((const float2*)(h + (size_t)idx[j] * D_FEAT))[lane];
    float p[CH];
    #pragma unroll
    for (int j = 0; j < CH; ++j) p[j] = r[j].x * a.x + r[j].y * a.y;
    #pragma unroll
    for (int off = 16; off; off >>= 1) {
        #pragma unroll
        for (int j = 0; j < CH; ++j)
            p[j] += __shfl_xor_sync(0xffffffffu, p[j], off);
    }
    #pragma unroll
    for (int j = 0; j < CH; ++j) {
        float ev = fmaxf(p[j], 0.f);
        float mn = fmaxf(m, ev);
        float cc = __expf(m - mn);
        float w  = __expf(ev - mn);
        s    = s    * cc + w;
        acc0 = acc0 * cc + r[j].x * w;
        acc1 = acc1 * cc + r[j].y * w;
        m = mn;
    }
}

__global__ void k_gather(const float* __restrict__ h,
                         const float* __restrict__ attn) {
    int gw   = (blockIdx.x * blockDim.x + threadIdx.x) >> 5;
    int lane = threadIdx.x & 31;
    if (gw >= g_uniq_count) return;
    int n   = g_uniq[gw];
    int cnt = g_cnt[gw];
    if (cnt > ECAP) cnt = ECAP;

    float2 a = ((const float2*)attn)[lane];
    const int* es = g_es + (size_t)gw * ECAP;

    float m = -1e30f, s = 0.f, acc0 = 0.f, acc1 = 0.f;
    int base = 0, rem = cnt;
    while (rem >= 8) { gather_chunk<8>(h, es, base, a, lane, m, s, acc0, acc1); base += 8; rem -= 8; }
    if (rem >= 4)    { gather_chunk<4>(h, es, base, a, lane, m, s, acc0, acc1); base += 4; rem -= 4; }
    if (rem >= 2)    { gather_chunk<2>(h, es, base, a, lane, m, s, acc0, acc1); base += 2; rem -= 2; }
    if (rem)         { gather_chunk<1>(h, es, base, a, lane, m, s, acc0, acc1); }

    float inv = (s > 0.f) ? (1.0f / s) : 0.f;
    ((float2*)(g_hneigh + (size_t)n * D_FEAT))[lane] = make_float2(acc0 * inv, acc1 * inv);
}

// ---------------- mma.sync helpers ---------------------------------------------
__device__ __forceinline__ uint32_t smem_u32(const void* p) {
    uint32_t a;
    asm("{ .reg .u64 t; cvta.to.shared.u64 t, %1; cvt.u32.u64 %0, t; }" : "=r"(a) : "l"(p));
    return a;
}
__device__ __forceinline__ void ldm4t(uint32_t addr, uint32_t& r0, uint32_t& r1,
                                      uint32_t& r2, uint32_t& r3) {
    asm volatile("ldmatrix.sync.aligned.m8n8.x4.trans.shared.b16 {%0,%1,%2,%3}, [%4];"
                 : "=r"(r0), "=r"(r1), "=r"(r2), "=r"(r3) : "r"(addr));
}
__device__ __forceinline__ void mma16816h(float c[4],
                                          uint32_t a0, uint32_t a1, uint32_t a2, uint32_t a3,
                                          uint32_t b0, uint32_t b1) {
    asm volatile(
        "mma.sync.aligned.m16n8k16.row.col.f32.f16.f16.f32 "
        "{%0,%1,%2,%3}, {%4,%5,%6,%7}, {%8,%9}, {%0,%1,%2,%3};"
        : "+f"(c[0]), "+f"(c[1]), "+f"(c[2]), "+f"(c[3])
        : "r"(a0), "r"(a1), "r"(a2), "r"(a3), "r"(b0), "r"(b1));
}
__device__ __forceinline__ uint32_t packh2(__half a, __half b) {
    __half2 h = __halves2half2(a, b);
    return *(uint32_t*)&h;
}

// ---------------- K5: fused dual-path MLP, 384 thr, M=16/warp, 192 rows/CTA -----
#define XS    72
#define W1S   264
#define W2S   72
#define NROWS 192
#define NTHR  384
#define OFF_XH   0          // 27648
#define OFF_XL   27648      // 27648
#define OFF_W1S_ 55296      // 33792
#define OFF_W2S_ 89088      // 36864
#define OFF_W1N_ 125952     // 33792
#define OFF_W2N_ 159744     // 36864
#define OFF_B1   196608     // 2048 (256 floats x 2 paths)
#define OFF_B2   198656     // 256
#define SMEM_TOTAL 198912

__global__ void __launch_bounds__(NTHR, 1)
k_mlp_fused(const float* __restrict__ cell,
            const float* __restrict__ Ws1, const float* __restrict__ bs1,
            const float* __restrict__ Ws2,
            const float* __restrict__ Wn1, const float* __restrict__ bn1,
            const float* __restrict__ Wn2,
            const float* __restrict__ bs2, const float* __restrict__ bn2,
            const int*   __restrict__ targets,
            float* __restrict__ out, int T) {
    extern __shared__ char smem[];
    const uint32_t sb = smem_u32(smem);

    const int tid  = threadIdx.x;
    const int lane = tid & 31;
    const int warp = tid >> 5;
    const int g = lane >> 2;
    const int t = lane & 3;
    const int R0 = warp * 16;

    const int lr = (lane & 7) + ((lane >> 3) & 1) * 8;
    const int lc = (lane >> 4) * 8;

    // ---- stage both paths' weights + biases (once per CTA) ----
    {
        const float4* w1s = (const float4*)Ws1;
        const float4* w1n = (const float4*)Wn1;
        for (int u = tid; u < 4096; u += NTHR) {
            int j = u * 4;
            int k = j >> 8, n = j & 255;
            uint32_t off = (k * W1S + n) * 2;
            float4 vs = w1s[u];
            float4 vn = w1n[u];
            *(uint32_t*)(smem + OFF_W1S_ + off)     = packh2(__float2half(vs.x), __float2half(vs.y));
            *(uint32_t*)(smem + OFF_W1S_ + off + 4) = packh2(__float2half(vs.z), __float2half(vs.w));
            *(uint32_t*)(smem + OFF_W1N_ + off)     = packh2(__float2half(vn.x), __float2half(vn.y));
            *(uint32_t*)(smem + OFF_W1N_ + off + 4) = packh2(__float2half(vn.z), __float2half(vn.w));
        }
        const float4* w2s = (const float4*)Ws2;
        const float4* w2n = (const float4*)Wn2;
        for (int u = tid; u < 4096; u += NTHR) {
            int j = u * 4;
            int k = j >> 6, n = j & 63;
            uint32_t off = (k * W2S + n) * 2;
            float4 vs = w2s[u];
            float4 vn = w2n[u];
            *(uint32_t*)(smem + OFF_W2S_ + off)     = packh2(__float2half(vs.x), __float2half(vs.y));
            *(uint32_t*)(smem + OFF_W2S_ + off + 4) = packh2(__float2half(vs.z), __float2half(vs.w));
            *(uint32_t*)(smem + OFF_W2N_ + off)     = packh2(__float2half(vn.x), __float2half(vn.y));
            *(uint32_t*)(smem + OFF_W2N_ + off + 4) = packh2(__float2half(vn.z), __float2half(vn.w));
        }
        if (tid < 256) {
            ((float*)(smem + OFF_B1))[tid]       = bs1[tid];
            ((float*)(smem + OFF_B1))[tid + 256] = bn1[tid];
        }
        if (tid < 64) ((float*)(smem + OFF_B2))[tid] = bs2[tid] + bn2[tid];
    }

    // node for this thread's staging row (2 threads per row)
    const int row_mine = tid >> 1;
    size_t tgt = (size_t)blockIdx.x * NROWS + row_mine;
    if (tgt >= (size_t)T) tgt = (size_t)T - 1;
    const int node = targets[tgt];

    float o[8][4];
    #pragma unroll
    for (int j = 0; j < 8; ++j)
        #pragma unroll
        for (int q = 0; q < 4; ++q) o[j][q] = 0.f;

    #pragma unroll 1
    for (int p = 0; p < 2; ++p) {
        __syncthreads();   // previous path done reading X (and W ready on p=0)

        // ---- stage X (fp16 hi/lo), 2 threads per row ----
        {
            const float* xr = p ? (g_hneigh + (size_t)node * 64)
                                : (cell     + (size_t)node * 64);
            const float4* xv = (const float4*)(xr + (tid & 1) * 32);
            uint32_t base = row_mine * XS + (tid & 1) * 32;
            #pragma unroll
            for (int q = 0; q < 8; ++q) {
                float4 v = xv[q];
                __half h0 = __float2half(v.x), h1 = __float2half(v.y);
                __half h2 = __float2half(v.z), h3 = __float2half(v.w);
                float l0 = v.x - __half2float(h0), l1 = v.y - __half2float(h1);
                float l2 = v.z - __half2float(h2), l3 = v.w - __half2float(h3);
                uint32_t off = (base + 4 * q) * 2;
                *(uint32_t*)(smem + OFF_XH + off)     = packh2(h0, h1);
                *(uint32_t*)(smem + OFF_XH + off + 4) = packh2(h2, h3);
                *(uint32_t*)(smem + OFF_XL + off)     = packh2(__float2half(l0), __float2half(l1));
                *(uint32_t*)(smem + OFF_XL + off + 4) = packh2(__float2half(l2), __float2half(l3));
            }
        }
        __syncthreads();

        // ---- A1 fragments: K=64, hi & lo ----
        uint32_t a1h[4][4], a1l[4][4];
        #pragma unroll
        for (int kk = 0; kk < 4; ++kk) {
            uint32_t c0 = ((R0 + g) * XS + kk * 16 + 2 * t) * 2;
            uint32_t c1 = c0 + 8 * XS * 2;
            a1h[kk][0] = *(uint32_t*)(smem + OFF_XH + c0);
            a1h[kk][1] = *(uint32_t*)(smem + OFF_XH + c1);
            a1h[kk][2] = *(uint32_t*)(smem + OFF_XH + c0 + 16);
            a1h[kk][3] = *(uint32_t*)(smem + OFF_XH + c1 + 16);
            a1l[kk][0] = *(uint32_t*)(smem + OFF_XL + c0);
            a1l[kk][1] = *(uint32_t*)(smem + OFF_XL + c1);
            a1l[kk][2] = *(uint32_t*)(smem + OFF_XL + c0 + 16);
            a1l[kk][3] = *(uint32_t*)(smem + OFF_XL + c1 + 16);
        }

        const float* b1s = (const float*)(smem + OFF_B1) + p * 256;
        const uint32_t w1a = sb + (p ? OFF_W1N_ : OFF_W1S_);
        const uint32_t w2a = sb + (p ? OFF_W2N_ : OFF_W2S_);

        #pragma unroll 1
        for (int n16 = 0; n16 < 16; ++n16) {
            float c[2][4];
            #pragma unroll
            for (int hh = 0; hh < 2; ++hh)
                #pragma unroll
                for (int q = 0; q < 4; ++q) c[hh][q] = 0.f;

            // ---- layer 1 (Ah*B + Al*B) ----
            #pragma unroll
            for (int kk = 0; kk < 4; ++kk) {
                uint32_t lm = ((kk * 16 + lr) * W1S + n16 * 16 + lc) * 2;
                uint32_t b0, b1, b2, b3;
                ldm4t(w1a + lm, b0, b1, b2, b3);
                mma16816h(c[0], a1h[kk][0], a1h[kk][1], a1h[kk][2], a1h[kk][3], b0, b1);
                mma16816h(c[1], a1h[kk][0], a1h[kk][1], a1h[kk][2], a1h[kk][3], b2, b3);
                mma16816h(c[0], a1l[kk][0], a1l[kk][1], a1l[kk][2], a1l[kk][3], b0, b1);
                mma16816h(c[1], a1l[kk][0], a1l[kk][1], a1l[kk][2], a1l[kk][3], b2, b3);
            }

            // ---- epilogue: +b1, relu, fp16 hi/lo split -> A2 frags ----
            uint32_t a2h[4], a2l[4];
            {
                float vb0 = b1s[n16 * 16 + 2 * t];
                float vb1 = b1s[n16 * 16 + 2 * t + 1];
                float vb2 = b1s[n16 * 16 + 8 + 2 * t];
                float vb3 = b1s[n16 * 16 + 8 + 2 * t + 1];
                float v[8];
                v[0] = fmaxf(c[0][0] + vb0, 0.f); v[1] = fmaxf(c[0][1] + vb1, 0.f);
                v[2] = fmaxf(c[0][2] + vb0, 0.f); v[3] = fmaxf(c[0][3] + vb1, 0.f);
                v[4] = fmaxf(c[1][0] + vb2, 0.f); v[5] = fmaxf(c[1][1] + vb3, 0.f);
                v[6] = fmaxf(c[1][2] + vb2, 0.f); v[7] = fmaxf(c[1][3] + vb3, 0.f);
                #pragma unroll
                for (int q = 0; q < 4; ++q) {
                    float v0 = v[2 * q], v1 = v[2 * q + 1];
                    __half h0 = __float2half(v0), h1 = __float2half(v1);
                    float l0 = v0 - __half2float(h0);
                    float l1 = v1 - __half2float(h1);
                    a2h[q] = packh2(h0, h1);
                    a2l[q] = packh2(__float2half(l0), __float2half(l1));
                }
            }

            // ---- layer 2 ----
            #pragma unroll
            for (int m = 0; m < 4; ++m) {
                uint32_t lm = ((n16 * 16 + lr) * W2S + m * 16 + lc) * 2;
                uint32_t b0, b1, b2, b3;
                ldm4t(w2a + lm, b0, b1, b2, b3);
                mma16816h(o[2 * m],     a2h[0], a2h[1], a2h[2], a2h[3], b0, b1);
                mma16816h(o[2 * m + 1], a2h[0], a2h[1], a2h[2], a2h[3], b2, b3);
                mma16816h(o[2 * m],     a2l[0], a2l[1], a2l[2], a2l[3], b0, b1);
                mma16816h(o[2 * m + 1], a2l[0], a2l[1], a2l[2], a2l[3], b2, b3);
            }
        }
    }

    // ---- final: + (bs2+bn2), relu, store ----
    const float* b2c = (const float*)(smem + OFF_B2);
    size_t r0 = (size_t)blockIdx.x * NROWS + R0 + g;
    size_t r1 = r0 + 8;
    #pragma unroll
    for (int j = 0; j < 8; ++j) {
        int col = 8 * j + 2 * t;
        float bb0 = b2c[col], bb1 = b2c[col + 1];
        if (r0 < (size_t)T) {
            float2 v = make_float2(fmaxf(o[j][0] + bb0, 0.f), fmaxf(o[j][1] + bb1, 0.f));
            *(float2*)(out + r0 * 64 + col) = v;
        }
        if (r1 < (size_t)T) {
            float2 v = make_float2(fmaxf(o[j][2] + bb0, 0.f), fmaxf(o[j][3] + bb1, 0.f));
            *(float2*)(out + r1 * 64 + col) = v;
        }
    }
}

// ---------------- launch --------------------------------------------------------
extern "C" void kernel_launch(void* const* d_in, const int* in_sizes, int n_in,
                              void* d_out, int out_size) {
    const float* h    = (const float*)d_in[0];
    const float* cell = (const float*)d_in[1];
    const float* attn = (const float*)d_in[2];
    const float* Wn1  = (const float*)d_in[3];
    const float* bn1  = (const float*)d_in[4];
    const float* Wn2  = (const float*)d_in[5];
    const float* bn2  = (const float*)d_in[6];
    const float* Ws1  = (const float*)d_in[7];
    const float* bs1  = (const float*)d_in[8];
    const float* Ws2  = (const float*)d_in[9];
    const float* bs2  = (const float*)d_in[10];
    const int* src     = (const int*)d_in[11];
    const int* dst     = (const int*)d_in[12];
    const int* targets = (const int*)d_in[13];

    int N = in_sizes[0] / D_FEAT;
    int E = in_sizes[11];
    int T = in_sizes[13];
    float* out = (float*)d_out;

    k_init <<<(N + 255) / 256, 256>>>(N);
    k_mark <<<(T + 255) / 256, 256>>>(targets, T);
    k_build<<<(E + 255) / 256, 256>>>(src, dst, E);

    int gwarps = (T < N) ? T : N;
    k_gather<<<(gwarps + 7) / 8, 256>>>(h, attn);   // 4th launch -> profiled

    int mgrid = (T + NROWS - 1) / NROWS;
    cudaFuncSetAttribute(k_mlp_fused, cudaFuncAttributeMaxDynamicSharedMemorySize, SMEM_TOTAL);
    k_mlp_fused<<<mgrid, NTHR, SMEM_TOTAL>>>(cell, Ws1, bs1, Ws2,
                                             Wn1, bn1, Wn2,
                                             bs2, bn2, targets, out, T);
}

// round 15
// speedup vs baseline: 1.8998x; 1.4895x over previous
#include <cuda_runtime.h>
#include <cuda_fp16.h>
#include <math.h>
#include <stdint.h>

#define D_FEAT 64
#define HID    256
#define NMAX   500000
#define EMAX   2000000
#define ECAP   64

// ---------------- scratch (static device globals) -----------------------------
__device__ int   g_flag[NMAX];
__device__ int   g_cnt[NMAX];
__device__ int   g_uniq[NMAX];
__device__ int   g_uniq_count;
__device__ int   g_es[(size_t)NMAX * ECAP];
__device__ __align__(256) float g_hneigh[(size_t)NMAX * D_FEAT];

// ---------------- K1: init -----------------------------------------------------
__global__ void k_init(int N) {
    int i = blockIdx.x * blockDim.x + threadIdx.x;
    if (i == 0) g_uniq_count = 0;
    if (i < N) { g_flag[i] = 0; g_cnt[i] = 0; }
}

// ---------------- K2: mark targets, assign compact uids ------------------------
__global__ void k_mark(const int* __restrict__ targets, int T) {
    int i = blockIdx.x * blockDim.x + threadIdx.x;
    if (i < T) {
        int n = targets[i];
        if (atomicCAS(&g_flag[n], 0, 1) == 0) {
            int p = atomicAdd(&g_uniq_count, 1);
            g_uniq[p] = n;
            g_flag[n] = p + 2;
        }
    }
}

// ---------------- K3: bucket flagged edges into per-uid slot arrays ------------
__global__ void k_build(const int* __restrict__ src, const int* __restrict__ dst, int E) {
    int e = blockIdx.x * blockDim.x + threadIdx.x;
    if (e < E) {
        int f = g_flag[dst[e]];
        if (f >= 2) {
            int uid  = f - 2;
            int slot = atomicAdd(&g_cnt[uid], 1);
            if (slot < ECAP) g_es[(size_t)uid * ECAP + slot] = src[e];
        }
    }
}

// ---------------- K4: 2 nodes/warp (16 lanes each), batch-max online softmax ---
__global__ void k_gather(const float* __restrict__ h,
                         const float* __restrict__ attn) {
    int gw   = (blockIdx.x * blockDim.x + threadIdx.x) >> 5;
    int lane = threadIdx.x & 31;
    int half = lane >> 4;
    int sub  = lane & 15;

    int count = g_uniq_count;
    if (gw * 2 >= count) return;
    int ni = gw * 2 + half;
    bool vn = ni < count;
    int ni_c = vn ? ni : (count - 1);

    int n   = g_uniq[ni_c];
    int cnt = vn ? g_cnt[ni_c] : 0;
    if (cnt > ECAP) cnt = ECAP;

    float4 a = ((const float4*)attn)[sub];
    const int* es = g_es + (size_t)ni_c * ECAP;

    // both halves iterate the same number of chunks (keep warp converged)
    int cnt_o = __shfl_xor_sync(0xffffffffu, cnt, 16);
    int mc = cnt > cnt_o ? cnt : cnt_o;

    float m = -1e30f, s = 0.f;
    float4 acc = make_float4(0.f, 0.f, 0.f, 0.f);

    for (int base = 0; base < mc; base += 4) {
        int idx[4];
        float4 r[4];
        float p[4];
        #pragma unroll
        for (int j = 0; j < 4; ++j) {
            bool v = (base + j) < cnt;
            idx[j] = v ? es[base + j] : 0;
        }
        #pragma unroll
        for (int j = 0; j < 4; ++j)
            r[j] = *(const float4*)(h + (size_t)idx[j] * D_FEAT + sub * 4);
        #pragma unroll
        for (int j = 0; j < 4; ++j)
            p[j] = r[j].x * a.x + r[j].y * a.y + r[j].z * a.z + r[j].w * a.w;
        #pragma unroll
        for (int off = 8; off; off >>= 1) {
            #pragma unroll
            for (int j = 0; j < 4; ++j)
                p[j] += __shfl_xor_sync(0xffffffffu, p[j], off);
        }
        float ev[4];
        #pragma unroll
        for (int j = 0; j < 4; ++j)
            ev[j] = ((base + j) < cnt) ? fmaxf(p[j], 0.f) : -1e30f;

        float cmax = fmaxf(fmaxf(ev[0], ev[1]), fmaxf(ev[2], ev[3]));
        float mn = fmaxf(m, cmax);
        float w[4];
        #pragma unroll
        for (int j = 0; j < 4; ++j)
            w[j] = ((base + j) < cnt) ? __expf(ev[j] - mn) : 0.f;
        float cc = __expf(m - mn);
        m = mn;
        s = s * cc + (w[0] + w[1]) + (w[2] + w[3]);
        acc.x = acc.x * cc + w[0]*r[0].x + w[1]*r[1].x + w[2]*r[2].x + w[3]*r[3].x;
        acc.y = acc.y * cc + w[0]*r[0].y + w[1]*r[1].y + w[2]*r[2].y + w[3]*r[3].y;
        acc.z = acc.z * cc + w[0]*r[0].z + w[1]*r[1].z + w[2]*r[2].z + w[3]*r[3].z;
        acc.w = acc.w * cc + w[0]*r[0].w + w[1]*r[1].w + w[2]*r[2].w + w[3]*r[3].w;
    }

    float inv = (s > 0.f) ? (1.0f / s) : 0.f;
    if (vn) {
        float4 o = make_float4(acc.x * inv, acc.y * inv, acc.z * inv, acc.w * inv);
        *(float4*)(g_hneigh + (size_t)n * D_FEAT + sub * 4) = o;
    }
}

// ---------------- mma.sync helpers ---------------------------------------------
__device__ __forceinline__ uint32_t smem_u32(const void* p) {
    uint32_t a;
    asm("{ .reg .u64 t; cvta.to.shared.u64 t, %1; cvt.u32.u64 %0, t; }" : "=r"(a) : "l"(p));
    return a;
}
__device__ __forceinline__ void ldm4t(uint32_t addr, uint32_t& r0, uint32_t& r1,
                                      uint32_t& r2, uint32_t& r3) {
    asm volatile("ldmatrix.sync.aligned.m8n8.x4.trans.shared.b16 {%0,%1,%2,%3}, [%4];"
                 : "=r"(r0), "=r"(r1), "=r"(r2), "=r"(r3) : "r"(addr));
}
__device__ __forceinline__ void mma16816h(float c[4],
                                          uint32_t a0, uint32_t a1, uint32_t a2, uint32_t a3,
                                          uint32_t b0, uint32_t b1) {
    asm volatile(
        "mma.sync.aligned.m16n8k16.row.col.f32.f16.f16.f32 "
        "{%0,%1,%2,%3}, {%4,%5,%6,%7}, {%8,%9}, {%0,%1,%2,%3};"
        : "+f"(c[0]), "+f"(c[1]), "+f"(c[2]), "+f"(c[3])
        : "r"(a0), "r"(a1), "r"(a2), "r"(a3), "r"(b0), "r"(b1));
}
__device__ __forceinline__ uint32_t packh2(__half a, __half b) {
    __half2 h = __halves2half2(a, b);
    return *(uint32_t*)&h;
}

// ---------------- K5: fused dual-path MLP, 512 thr, single fp16 term ------------
#define XS    72
#define W1S   264
#define W2S   72
#define NROWS 256
#define NTHR  512
#define OFF_X    0          // 36864
#define OFF_W1S_ 36864      // 33792
#define OFF_W2S_ 70656      // 36864
#define OFF_W1N_ 107520     // 33792
#define OFF_W2N_ 141312     // 36864
#define OFF_B1   178176     // 2048
#define OFF_B2   180224     // 256
#define SMEM_TOTAL 180480

__global__ void __launch_bounds__(NTHR, 1)
k_mlp_fused(const float* __restrict__ cell,
            const float* __restrict__ Ws1, const float* __restrict__ bs1,
            const float* __restrict__ Ws2,
            const float* __restrict__ Wn1, const float* __restrict__ bn1,
            const float* __restrict__ Wn2,
            const float* __restrict__ bs2, const float* __restrict__ bn2,
            const int*   __restrict__ targets,
            float* __restrict__ out, int T) {
    extern __shared__ char smem[];
    const uint32_t sb = smem_u32(smem);

    const int tid  = threadIdx.x;
    const int lane = tid & 31;
    const int warp = tid >> 5;
    const int g = lane >> 2;
    const int t = lane & 3;
    const int R0 = warp * 16;

    const int lr = (lane & 7) + ((lane >> 3) & 1) * 8;
    const int lc = (lane >> 4) * 8;

    // ---- stage both paths' weights + biases (once per CTA) ----
    {
        const float4* w1s = (const float4*)Ws1;
        const float4* w1n = (const float4*)Wn1;
        #pragma unroll
        for (int i = 0; i < 8; ++i) {
            int u = tid + NTHR * i;
            int j = u * 4;
            int k = j >> 8, n = j & 255;
            uint32_t off = (k * W1S + n) * 2;
            float4 vs = w1s[u];
            float4 vn = w1n[u];
            *(uint32_t*)(smem + OFF_W1S_ + off)     = packh2(__float2half(vs.x), __float2half(vs.y));
            *(uint32_t*)(smem + OFF_W1S_ + off + 4) = packh2(__float2half(vs.z), __float2half(vs.w));
            *(uint32_t*)(smem + OFF_W1N_ + off)     = packh2(__float2half(vn.x), __float2half(vn.y));
            *(uint32_t*)(smem + OFF_W1N_ + off + 4) = packh2(__float2half(vn.z), __float2half(vn.w));
        }
        const float4* w2s = (const float4*)Ws2;
        const float4* w2n = (const float4*)Wn2;
        #pragma unroll
        for (int i = 0; i < 8; ++i) {
            int u = tid + NTHR * i;
            int j = u * 4;
            int k = j >> 6, n = j & 63;
            uint32_t off = (k * W2S + n) * 2;
            float4 vs = w2s[u];
            float4 vn = w2n[u];
            *(uint32_t*)(smem + OFF_W2S_ + off)     = packh2(__float2half(vs.x), __float2half(vs.y));
            *(uint32_t*)(smem + OFF_W2S_ + off + 4) = packh2(__float2half(vs.z), __float2half(vs.w));
            *(uint32_t*)(smem + OFF_W2N_ + off)     = packh2(__float2half(vn.x), __float2half(vn.y));
            *(uint32_t*)(smem + OFF_W2N_ + off + 4) = packh2(__float2half(vn.z), __float2half(vn.w));
        }
        {
            int pp = tid >> 8, idx = tid & 255;
            ((float*)(smem + OFF_B1))[tid] = pp ? bn1[idx] : bs1[idx];
        }
        if (tid < 64) ((float*)(smem + OFF_B2))[tid] = bs2[tid] + bn2[tid];
    }

    // node for this thread's staging row (2 threads per row)
    const int row_mine = tid >> 1;
    size_t tgt = (size_t)blockIdx.x * NROWS + row_mine;
    if (tgt >= (size_t)T) tgt = (size_t)T - 1;
    const int node = targets[tgt];

    float o[8][4];
    #pragma unroll
    for (int j = 0; j < 8; ++j)
        #pragma unroll
        for (int q = 0; q < 4; ++q) o[j][q] = 0.f;

    #pragma unroll 1
    for (int p = 0; p < 2; ++p) {
        __syncthreads();   // previous path done reading X (and W ready on p=0)

        // ---- stage X (single fp16), 2 threads per row ----
        {
            const float* xr = p ? (g_hneigh + (size_t)node * 64)
                                : (cell     + (size_t)node * 64);
            const float4* xv = (const float4*)(xr + (tid & 1) * 32);
            uint32_t base = row_mine * XS + (tid & 1) * 32;
            #pragma unroll
            for (int q = 0; q < 8; ++q) {
                float4 v = xv[q];
                uint32_t off = (base + 4 * q) * 2;
                *(uint32_t*)(smem + OFF_X + off)     = packh2(__float2half(v.x), __float2half(v.y));
                *(uint32_t*)(smem + OFF_X + off + 4) = packh2(__float2half(v.z), __float2half(v.w));
            }
        }
        __syncthreads();

        // ---- A1 fragments: K=64 ----
        uint32_t a1[4][4];
        #pragma unroll
        for (int kk = 0; kk < 4; ++kk) {
            uint32_t c0 = ((R0 + g) * XS + kk * 16 + 2 * t) * 2;
            uint32_t c1 = c0 + 8 * XS * 2;
            a1[kk][0] = *(uint32_t*)(smem + OFF_X + c0);
            a1[kk][1] = *(uint32_t*)(smem + OFF_X + c1);
            a1[kk][2] = *(uint32_t*)(smem + OFF_X + c0 + 16);
            a1[kk][3] = *(uint32_t*)(smem + OFF_X + c1 + 16);
        }

        const float* b1s = (const float*)(smem + OFF_B1) + p * 256;
        const uint32_t w1a = sb + (p ? OFF_W1N_ : OFF_W1S_);
        const uint32_t w2a = sb + (p ? OFF_W2N_ : OFF_W2S_);

        #pragma unroll 1
        for (int n16 = 0; n16 < 16; ++n16) {
            float c[2][4];
            #pragma unroll
            for (int hh = 0; hh < 2; ++hh)
                #pragma unroll
                for (int q = 0; q < 4; ++q) c[hh][q] = 0.f;

            // ---- layer 1 ----
            #pragma unroll
            for (int kk = 0; kk < 4; ++kk) {
                uint32_t lm = ((kk * 16 + lr) * W1S + n16 * 16 + lc) * 2;
                uint32_t b0, b1, b2, b3;
                ldm4t(w1a + lm, b0, b1, b2, b3);
                mma16816h(c[0], a1[kk][0], a1[kk][1], a1[kk][2], a1[kk][3], b0, b1);
                mma16816h(c[1], a1[kk][0], a1[kk][1], a1[kk][2], a1[kk][3], b2, b3);
            }

            // ---- epilogue: +b1, relu, fp16 pack -> A2 frags ----
            uint32_t a2[4];
            {
                float vb0 = b1s[n16 * 16 + 2 * t];
                float vb1 = b1s[n16 * 16 + 2 * t + 1];
                float vb2 = b1s[n16 * 16 + 8 + 2 * t];
                float vb3 = b1s[n16 * 16 + 8 + 2 * t + 1];
                a2[0] = packh2(__float2half(fmaxf(c[0][0] + vb0, 0.f)),
                               __float2half(fmaxf(c[0][1] + vb1, 0.f)));
                a2[1] = packh2(__float2half(fmaxf(c[0][2] + vb0, 0.f)),
                               __float2half(fmaxf(c[0][3] + vb1, 0.f)));
                a2[2] = packh2(__float2half(fmaxf(c[1][0] + vb2, 0.f)),
                               __float2half(fmaxf(c[1][1] + vb3, 0.f)));
                a2[3] = packh2(__float2half(fmaxf(c[1][2] + vb2, 0.f)),
                               __float2half(fmaxf(c[1][3] + vb3, 0.f)));
            }

            // ---- layer 2 ----
            #pragma unroll
            for (int m = 0; m < 4; ++m) {
                uint32_t lm = ((n16 * 16 + lr) * W2S + m * 16 + lc) * 2;
                uint32_t b0, b1, b2, b3;
                ldm4t(w2a + lm, b0, b1, b2, b3);
                mma16816h(o[2 * m],     a2[0], a2[1], a2[2], a2[3], b0, b1);
                mma16816h(o[2 * m + 1], a2[0], a2[1], a2[2], a2[3], b2, b3);
            }
        }
    }

    // ---- final: + (bs2+bn2), relu, store ----
    const float* b2c = (const float*)(smem + OFF_B2);
    size_t r0 = (size_t)blockIdx.x * NROWS + R0 + g;
    size_t r1 = r0 + 8;
    #pragma unroll
    for (int j = 0; j < 8; ++j) {
        int col = 8 * j + 2 * t;
        float bb0 = b2c[col], bb1 = b2c[col + 1];
        if (r0 < (size_t)T) {
            float2 v = make_float2(fmaxf(o[j][0] + bb0, 0.f), fmaxf(o[j][1] + bb1, 0.f));
            *(float2*)(out + r0 * 64 + col) = v;
        }
        if (r1 < (size_t)T) {
            float2 v = make_float2(fmaxf(o[j][2] + bb0, 0.f), fmaxf(o[j][3] + bb1, 0.f));
            *(float2*)(out + r1 * 64 + col) = v;
        }
    }
}

// ---------------- launch --------------------------------------------------------
extern "C" void kernel_launch(void* const* d_in, const int* in_sizes, int n_in,
                              void* d_out, int out_size) {
    const float* h    = (const float*)d_in[0];
    const float* cell = (const float*)d_in[1];
    const float* attn = (const float*)d_in[2];
    const float* Wn1  = (const float*)d_in[3];
    const float* bn1  = (const float*)d_in[4];
    const float* Wn2  = (const float*)d_in[5];
    const float* bn2  = (const float*)d_in[6];
    const float* Ws1  = (const float*)d_in[7];
    const float* bs1  = (const float*)d_in[8];
    const float* Ws2  = (const float*)d_in[9];
    const float* bs2  = (const float*)d_in[10];
    const int* src     = (const int*)d_in[11];
    const int* dst     = (const int*)d_in[12];
    const int* targets = (const int*)d_in[13];

    int N = in_sizes[0] / D_FEAT;
    int E = in_sizes[11];
    int T = in_sizes[13];
    float* out = (float*)d_out;

    k_init <<<(N + 255) / 256, 256>>>(N);
    k_mark <<<(T + 255) / 256, 256>>>(targets, T);
    k_build<<<(E + 255) / 256, 256>>>(src, dst, E);

    int maxnodes = (T < N) ? T : N;
    int gwarps = (maxnodes + 1) / 2;
    k_gather<<<(gwarps + 7) / 8, 256>>>(h, attn);   // 4th launch -> profiled

    int mgrid = (T + NROWS - 1) / NROWS;
    cudaFuncSetAttribute(k_mlp_fused, cudaFuncAttributeMaxDynamicSharedMemorySize, SMEM_TOTAL);
    k_mlp_fused<<<mgrid, NTHR, SMEM_TOTAL>>>(cell, Ws1, bs1, Ws2,
                                             Wn1, bn1, Wn2,
                                             bs2, bn2, targets, out, T);
}

// round 16
// speedup vs baseline: 1.9294x; 1.0156x over previous
#include <cuda_runtime.h>
#include <cuda_fp16.h>
#include <math.h>
#include <stdint.h>

#define D_FEAT 64
#define HID    256
#define NMAX   500000
#define EMAX   2000000
#define ECAP   64

// ---------------- scratch (static device globals) -----------------------------
__device__ int   g_flag[NMAX];
__device__ int   g_cnt[NMAX];
__device__ int   g_uniq[NMAX];
__device__ int   g_uniq_count;
__device__ int   g_es[(size_t)NMAX * ECAP];
__device__ __align__(256) float g_hneigh[(size_t)NMAX * D_FEAT];

// ---------------- K1: init -----------------------------------------------------
__global__ void k_init(int N) {
    int i = blockIdx.x * blockDim.x + threadIdx.x;
    if (i == 0) g_uniq_count = 0;
    if (i < N) { g_flag[i] = 0; g_cnt[i] = 0; }
}

// ---------------- K2: mark targets, assign compact uids ------------------------
__global__ void k_mark(const int* __restrict__ targets, int T) {
    int i = blockIdx.x * blockDim.x + threadIdx.x;
    if (i < T) {
        int n = targets[i];
        if (atomicCAS(&g_flag[n], 0, 1) == 0) {
            int p = atomicAdd(&g_uniq_count, 1);
            g_uniq[p] = n;
            g_flag[n] = p + 2;
        }
    }
}

// ---------------- K3: bucket flagged edges into per-uid slot arrays ------------
__global__ void k_build(const int* __restrict__ src, const int* __restrict__ dst, int E) {
    int e = blockIdx.x * blockDim.x + threadIdx.x;
    if (e < E) {
        int f = g_flag[dst[e]];
        if (f >= 2) {
            int uid  = f - 2;
            int slot = atomicAdd(&g_cnt[uid], 1);
            if (slot < ECAP) g_es[(size_t)uid * ECAP + slot] = src[e];
        }
    }
}

// ---------------- K4: 2 nodes/warp (16 lanes each), batch-max online softmax ---
__global__ void k_gather(const float* __restrict__ h,
                         const float* __restrict__ attn) {
    int gw   = (blockIdx.x * blockDim.x + threadIdx.x) >> 5;
    int lane = threadIdx.x & 31;
    int half = lane >> 4;
    int sub  = lane & 15;

    int count = g_uniq_count;
    if (gw * 2 >= count) return;
    int ni = gw * 2 + half;
    bool vn = ni < count;
    int ni_c = vn ? ni : (count - 1);

    int n   = g_uniq[ni_c];
    int cnt = vn ? g_cnt[ni_c] : 0;
    if (cnt > ECAP) cnt = ECAP;

    float4 a = ((const float4*)attn)[sub];
    const int* es = g_es + (size_t)ni_c * ECAP;

    // both halves iterate the same number of chunks (keep warp converged)
    int cnt_o = __shfl_xor_sync(0xffffffffu, cnt, 16);
    int mc = cnt > cnt_o ? cnt : cnt_o;

    float m = -1e30f, s = 0.f;
    float4 acc = make_float4(0.f, 0.f, 0.f, 0.f);

    for (int base = 0; base < mc; base += 4) {
        int idx[4];
        float4 r[4];
        float p[4];
        #pragma unroll
        for (int j = 0; j < 4; ++j) {
            bool v = (base + j) < cnt;
            idx[j] = v ? es[base + j] : 0;
        }
        #pragma unroll
        for (int j = 0; j < 4; ++j)
            r[j] = *(const float4*)(h + (size_t)idx[j] * D_FEAT + sub * 4);
        #pragma unroll
        for (int j = 0; j < 4; ++j)
            p[j] = r[j].x * a.x + r[j].y * a.y + r[j].z * a.z + r[j].w * a.w;
        #pragma unroll
        for (int off = 8; off; off >>= 1) {
            #pragma unroll
            for (int j = 0; j < 4; ++j)
                p[j] += __shfl_xor_sync(0xffffffffu, p[j], off);
        }
        float ev[4];
        #pragma unroll
        for (int j = 0; j < 4; ++j)
            ev[j] = ((base + j) < cnt) ? fmaxf(p[j], 0.f) : -1e30f;

        float cmax = fmaxf(fmaxf(ev[0], ev[1]), fmaxf(ev[2], ev[3]));
        float mn = fmaxf(m, cmax);
        float w[4];
        #pragma unroll
        for (int j = 0; j < 4; ++j)
            w[j] = ((base + j) < cnt) ? __expf(ev[j] - mn) : 0.f;
        float cc = __expf(m - mn);
        m = mn;
        s = s * cc + (w[0] + w[1]) + (w[2] + w[3]);
        acc.x = acc.x * cc + w[0]*r[0].x + w[1]*r[1].x + w[2]*r[2].x + w[3]*r[3].x;
        acc.y = acc.y * cc + w[0]*r[0].y + w[1]*r[1].y + w[2]*r[2].y + w[3]*r[3].y;
        acc.z = acc.z * cc + w[0]*r[0].z + w[1]*r[1].z + w[2]*r[2].z + w[3]*r[3].z;
        acc.w = acc.w * cc + w[0]*r[0].w + w[1]*r[1].w + w[2]*r[2].w + w[3]*r[3].w;
    }

    float inv = (s > 0.f) ? (1.0f / s) : 0.f;
    if (vn) {
        float4 o = make_float4(acc.x * inv, acc.y * inv, acc.z * inv, acc.w * inv);
        *(float4*)(g_hneigh + (size_t)n * D_FEAT + sub * 4) = o;
    }
}

// ---------------- mma.sync helpers ---------------------------------------------
__device__ __forceinline__ uint32_t smem_u32(const void* p) {
    uint32_t a;
    asm("{ .reg .u64 t; cvta.to.shared.u64 t, %1; cvt.u32.u64 %0, t; }" : "=r"(a) : "l"(p));
    return a;
}
__device__ __forceinline__ void ldm4t(uint32_t addr, uint32_t& r0, uint32_t& r1,
                                      uint32_t& r2, uint32_t& r3) {
    asm volatile("ldmatrix.sync.aligned.m8n8.x4.trans.shared.b16 {%0,%1,%2,%3}, [%4];"
                 : "=r"(r0), "=r"(r1), "=r"(r2), "=r"(r3) : "r"(addr));
}
__device__ __forceinline__ void mma16816h(float c[4],
                                          uint32_t a0, uint32_t a1, uint32_t a2, uint32_t a3,
                                          uint32_t b0, uint32_t b1) {
    asm volatile(
        "mma.sync.aligned.m16n8k16.row.col.f32.f16.f16.f32 "
        "{%0,%1,%2,%3}, {%4,%5,%6,%7}, {%8,%9}, {%0,%1,%2,%3};"
        : "+f"(c[0]), "+f"(c[1]), "+f"(c[2]), "+f"(c[3])
        : "r"(a0), "r"(a1), "r"(a2), "r"(a3), "r"(b0), "r"(b1));
}
__device__ __forceinline__ uint32_t packh2(__half a, __half b) {
    __half2 h = __halves2half2(a, b);
    return *(uint32_t*)&h;
}

// ---------------- K5: fused dual-path MLP, 512 thr, single fp16 term ------------
#define XS    72
#define W1S   264
#define W2S   72
#define NROWS 256
#define NTHR  512
#define OFF_X    0          // 36864
#define OFF_W1S_ 36864      // 33792
#define OFF_W2S_ 70656      // 36864
#define OFF_W1N_ 107520     // 33792
#define OFF_W2N_ 141312     // 36864
#define OFF_B1   178176     // 2048
#define OFF_B2   180224     // 256
#define SMEM_TOTAL 180480

__global__ void __launch_bounds__(NTHR, 1)
k_mlp_fused(const float* __restrict__ cell,
            const float* __restrict__ Ws1, const float* __restrict__ bs1,
            const float* __restrict__ Ws2,
            const float* __restrict__ Wn1, const float* __restrict__ bn1,
            const float* __restrict__ Wn2,
            const float* __restrict__ bs2, const float* __restrict__ bn2,
            const int*   __restrict__ targets,
            float* __restrict__ out, int T) {
    extern __shared__ char smem[];
    const uint32_t sb = smem_u32(smem);

    const int tid  = threadIdx.x;
    const int lane = tid & 31;
    const int warp = tid >> 5;
    const int g = lane >> 2;
    const int t = lane & 3;
    const int R0 = warp * 16;

    const int lr = (lane & 7) + ((lane >> 3) & 1) * 8;
    const int lc = (lane >> 4) * 8;

    // ---- stage both paths' weights + biases (once per CTA) ----
    {
        const float4* w1s = (const float4*)Ws1;
        const float4* w1n = (const float4*)Wn1;
        #pragma unroll
        for (int i = 0; i < 8; ++i) {
            int u = tid + NTHR * i;
            int j = u * 4;
            int k = j >> 8, n = j & 255;
            uint32_t off = (k * W1S + n) * 2;
            float4 vs = w1s[u];
            float4 vn = w1n[u];
            *(uint32_t*)(smem + OFF_W1S_ + off)     = packh2(__float2half(vs.x), __float2half(vs.y));
            *(uint32_t*)(smem + OFF_W1S_ + off + 4) = packh2(__float2half(vs.z), __float2half(vs.w));
            *(uint32_t*)(smem + OFF_W1N_ + off)     = packh2(__float2half(vn.x), __float2half(vn.y));
            *(uint32_t*)(smem + OFF_W1N_ + off + 4) = packh2(__float2half(vn.z), __float2half(vn.w));
        }
        const float4* w2s = (const float4*)Ws2;
        const float4* w2n = (const float4*)Wn2;
        #pragma unroll
        for (int i = 0; i < 8; ++i) {
            int u = tid + NTHR * i;
            int j = u * 4;
            int k = j >> 6, n = j & 63;
            uint32_t off = (k * W2S + n) * 2;
            float4 vs = w2s[u];
            float4 vn = w2n[u];
            *(uint32_t*)(smem + OFF_W2S_ + off)     = packh2(__float2half(vs.x), __float2half(vs.y));
            *(uint32_t*)(smem + OFF_W2S_ + off + 4) = packh2(__float2half(vs.z), __float2half(vs.w));
            *(uint32_t*)(smem + OFF_W2N_ + off)     = packh2(__float2half(vn.x), __float2half(vn.y));
            *(uint32_t*)(smem + OFF_W2N_ + off + 4) = packh2(__float2half(vn.z), __float2half(vn.w));
        }
        {
            int pp = tid >> 8, idx = tid & 255;
            ((float*)(smem + OFF_B1))[tid] = pp ? bn1[idx] : bs1[idx];
        }
        if (tid < 64) ((float*)(smem + OFF_B2))[tid] = bs2[tid] + bn2[tid];
    }

    // node for this thread's staging row (2 threads per row)
    const int row_mine = tid >> 1;
    size_t tgt = (size_t)blockIdx.x * NROWS + row_mine;
    if (tgt >= (size_t)T) tgt = (size_t)T - 1;
    const int node = targets[tgt];

    float o[8][4];
    #pragma unroll
    for (int j = 0; j < 8; ++j)
        #pragma unroll
        for (int q = 0; q < 4; ++q) o[j][q] = 0.f;

    #pragma unroll 1
    for (int p = 0; p < 2; ++p) {
        __syncthreads();   // previous path done reading X (and W ready on p=0)

        // ---- stage X (single fp16), 2 threads per row ----
        {
            const float* xr = p ? (g_hneigh + (size_t)node * 64)
                                : (cell     + (size_t)node * 64);
            const float4* xv = (const float4*)(xr + (tid & 1) * 32);
            uint32_t base = row_mine * XS + (tid & 1) * 32;
            #pragma unroll
            for (int q = 0; q < 8; ++q) {
                float4 v = xv[q];
                uint32_t off = (base + 4 * q) * 2;
                *(uint32_t*)(smem + OFF_X + off)     = packh2(__float2half(v.x), __float2half(v.y));
                *(uint32_t*)(smem + OFF_X + off + 4) = packh2(__float2half(v.z), __float2half(v.w));
            }
        }
        __syncthreads();

        // ---- A1 fragments: K=64 ----
        uint32_t a1[4][4];
        #pragma unroll
        for (int kk = 0; kk < 4; ++kk) {
            uint32_t c0 = ((R0 + g) * XS + kk * 16 + 2 * t) * 2;
            uint32_t c1 = c0 + 8 * XS * 2;
            a1[kk][0] = *(uint32_t*)(smem + OFF_X + c0);
            a1[kk][1] = *(uint32_t*)(smem + OFF_X + c1);
            a1[kk][2] = *(uint32_t*)(smem + OFF_X + c0 + 16);
            a1[kk][3] = *(uint32_t*)(smem + OFF_X + c1 + 16);
        }

        const float* b1s = (const float*)(smem + OFF_B1) + p * 256;
        const uint32_t w1a = sb + (p ? OFF_W1N_ : OFF_W1S_);
        const uint32_t w2a = sb + (p ? OFF_W2N_ : OFF_W2S_);

        #pragma unroll 1
        for (int n16 = 0; n16 < 16; ++n16) {
            float c[2][4];
            #pragma unroll
            for (int hh = 0; hh < 2; ++hh)
                #pragma unroll
                for (int q = 0; q < 4; ++q) c[hh][q] = 0.f;

            // ---- layer 1 ----
            #pragma unroll
            for (int kk = 0; kk < 4; ++kk) {
                uint32_t lm = ((kk * 16 + lr) * W1S + n16 * 16 + lc) * 2;
                uint32_t b0, b1, b2, b3;
                ldm4t(w1a + lm, b0, b1, b2, b3);
                mma16816h(c[0], a1[kk][0], a1[kk][1], a1[kk][2], a1[kk][3], b0, b1);
                mma16816h(c[1], a1[kk][0], a1[kk][1], a1[kk][2], a1[kk][3], b2, b3);
            }

            // ---- epilogue: +b1, relu, fp16 pack -> A2 frags ----
            uint32_t a2[4];
            {
                float vb0 = b1s[n16 * 16 + 2 * t];
                float vb1 = b1s[n16 * 16 + 2 * t + 1];
                float vb2 = b1s[n16 * 16 + 8 + 2 * t];
                float vb3 = b1s[n16 * 16 + 8 + 2 * t + 1];
                a2[0] = packh2(__float2half(fmaxf(c[0][0] + vb0, 0.f)),
                               __float2half(fmaxf(c[0][1] + vb1, 0.f)));
                a2[1] = packh2(__float2half(fmaxf(c[0][2] + vb0, 0.f)),
                               __float2half(fmaxf(c[0][3] + vb1, 0.f)));
                a2[2] = packh2(__float2half(fmaxf(c[1][0] + vb2, 0.f)),
                               __float2half(fmaxf(c[1][1] + vb3, 0.f)));
                a2[3] = packh2(__float2half(fmaxf(c[1][2] + vb2, 0.f)),
                               __float2half(fmaxf(c[1][3] + vb3, 0.f)));
            }

            // ---- layer 2 ----
            #pragma unroll
            for (int m = 0; m < 4; ++m) {
                uint32_t lm = ((n16 * 16 + lr) * W2S + m * 16 + lc) * 2;
                uint32_t b0, b1, b2, b3;
                ldm4t(w2a + lm, b0, b1, b2, b3);
                mma16816h(o[2 * m],     a2[0], a2[1], a2[2], a2[3], b0, b1);
                mma16816h(o[2 * m + 1], a2[0], a2[1], a2[2], a2[3], b2, b3);
            }
        }
    }

    // ---- final: + (bs2+bn2), relu, store ----
    const float* b2c = (const float*)(smem + OFF_B2);
    size_t r0 = (size_t)blockIdx.x * NROWS + R0 + g;
    size_t r1 = r0 + 8;
    #pragma unroll
    for (int j = 0; j < 8; ++j) {
        int col = 8 * j + 2 * t;
        float bb0 = b2c[col], bb1 = b2c[col + 1];
        if (r0 < (size_t)T) {
            float2 v = make_float2(fmaxf(o[j][0] + bb0, 0.f), fmaxf(o[j][1] + bb1, 0.f));
            *(float2*)(out + r0 * 64 + col) = v;
        }
        if (r1 < (size_t)T) {
            float2 v = make_float2(fmaxf(o[j][2] + bb0, 0.f), fmaxf(o[j][3] + bb1, 0.f));
            *(float2*)(out + r1 * 64 + col) = v;
        }
    }
}

// ---------------- launch --------------------------------------------------------
extern "C" void kernel_launch(void* const* d_in, const int* in_sizes, int n_in,
                              void* d_out, int out_size) {
    const float* h    = (const float*)d_in[0];
    const float* cell = (const float*)d_in[1];
    const float* attn = (const float*)d_in[2];
    const float* Wn1  = (const float*)d_in[3];
    const float* bn1  = (const float*)d_in[4];
    const float* Wn2  = (const float*)d_in[5];
    const float* bn2  = (const float*)d_in[6];
    const float* Ws1  = (const float*)d_in[7];
    const float* bs1  = (const float*)d_in[8];
    const float* Ws2  = (const float*)d_in[9];
    const float* bs2  = (const float*)d_in[10];
    const int* src     = (const int*)d_in[11];
    const int* dst     = (const int*)d_in[12];
    const int* targets = (const int*)d_in[13];

    int N = in_sizes[0] / D_FEAT;
    int E = in_sizes[11];
    int T = in_sizes[13];
    float* out = (float*)d_out;

    k_init <<<(N + 255) / 256, 256>>>(N);
    k_mark <<<(T + 255) / 256, 256>>>(targets, T);
    k_build<<<(E + 255) / 256, 256>>>(src, dst, E);

    int maxnodes = (T < N) ? T : N;
    int gwarps = (maxnodes + 1) / 2;
    k_gather<<<(gwarps + 7) / 8, 256>>>(h, attn);   // 4th launch -> profiled

    int mgrid = (T + NROWS - 1) / NROWS;
    cudaFuncSetAttribute(k_mlp_fused, cudaFuncAttributeMaxDynamicSharedMemorySize, SMEM_TOTAL);
    k_mlp_fused<<<mgrid, NTHR, SMEM_TOTAL>>>(cell, Ws1, bs1, Ws2,
                                             Wn1, bn1, Wn2,
                                             bs2, bn2, targets, out, T);
}